// round 16
// baseline (speedup 1.0000x reference)
#include <cuda_runtime.h>
#include <cuda_fp16.h>
#include <stdint.h>
#include <math.h>

#define BATCH 4
#define TLEN 2048
#define INPUT_DIM 256
#define D_MODEL 512
#define D_INNER 1024
#define NHEADS 8
#define HEADDIM 128
#define DSTATE 16
#define DCONV 4
#define CONV_DIM (D_INNER + 2*DSTATE)                 // 1056
#define D_IN_PROJ (2*D_INNER + 2*DSTATE + NHEADS)     // 2088
#define ZH_COLS (2*D_INNER)                           // 2048 fp16 cols (z|x)
#define ZT_COLS 64                                    // padded fp32 tail (B|C|dt = 40)
#define NLAYERS 4
#define GB (2*BATCH)          // 8
#define BT (BATCH*TLEN)       // 8192
#define GBT (GB*TLEN)         // 16384
#define LN_EPS 1e-5f
#define CHUNK 128
#define NCH (TLEN / CHUNK)    // 16

// ---------------- scratch ----------------
__device__ __align__(128) float  g_H  [(size_t)GBT * D_MODEL];
__device__ __align__(128) __half g_Hh [(size_t)GBT * D_MODEL];
__device__ __align__(128) __half g_Zh [(size_t)GBT * ZH_COLS];     // z|x fp16
__device__ __align__(128) float  g_Zt [(size_t)GBT * ZT_COLS];     // B|C|dt fp32
__device__ __align__(128) float  g_BC [(size_t)GBT * 2 * DSTATE];
__device__ __align__(128) float  g_dA [(size_t)GBT * NHEADS];
__device__ __align__(128) float  g_dt [(size_t)GBT * NHEADS];
__device__ __align__(128) __half g_Yh [(size_t)GBT * D_INNER];
__device__ __align__(128) __half g_Gh [(size_t)GBT * D_INNER];
__device__ __align__(128) float  g_tmp[(size_t)BT  * D_MODEL];
__device__ __align__(128) __half g_xh [(size_t)BT * INPUT_DIM];
__device__ __align__(128) __half g_ewh[(size_t)D_MODEL * INPUT_DIM];
__device__ __align__(128) __half g_iwh[(size_t)2 * NLAYERS * D_IN_PROJ * D_MODEL];
__device__ __align__(128) __half g_owh[(size_t)2 * NLAYERS * D_MODEL * D_INNER];
// chunked-scan scratch
__device__ __align__(128) float  g_E [(size_t)GB * NHEADS * NCH * HEADDIM * DSTATE];
__device__ __align__(128) float  g_S0[(size_t)GB * NHEADS * NCH * HEADDIM * DSTATE];
__device__ __align__(128) float  g_Pf[GB * NHEADS * NCH];

// ---------------- helpers ----------------
__device__ __forceinline__ float siluf(float v) { return v / (1.f + expf(-v)); }
__device__ __forceinline__ float softplusf(float v) { return v > 20.f ? v : log1pf(expf(v)); }

__device__ __forceinline__ uint32_t smem_u32(const void* p) {
    uint32_t a;
    asm("{ .reg .u64 t; cvta.to.shared.u64 t, %1; cvt.u32.u64 %0, t; }" : "=r"(a) : "l"(p));
    return a;
}
__device__ __forceinline__ void cp16(uint32_t dst, const void* src) {
    asm volatile("cp.async.cg.shared.global [%0], [%1], 16;" :: "r"(dst), "l"(src) : "memory");
}
#define SWZ(off) ((off) ^ (((off) >> 3) & 0x70))

__device__ __forceinline__ void block_reduce2(float& v0, float& v1)
{
    __shared__ float s0[32], s1[32];
    int lane = threadIdx.x & 31, wid = threadIdx.x >> 5;
    #pragma unroll
    for (int o = 16; o > 0; o >>= 1) {
        v0 += __shfl_xor_sync(0xffffffffu, v0, o);
        v1 += __shfl_xor_sync(0xffffffffu, v1, o);
    }
    if (lane == 0) { s0[wid] = v0; s1[wid] = v1; }
    __syncthreads();
    int nw = blockDim.x >> 5;
    if (wid == 0) {
        v0 = (lane < nw) ? s0[lane] : 0.f;
        v1 = (lane < nw) ? s1[lane] : 0.f;
        #pragma unroll
        for (int o = 16; o > 0; o >>= 1) {
            v0 += __shfl_xor_sync(0xffffffffu, v0, o);
            v1 += __shfl_xor_sync(0xffffffffu, v1, o);
        }
        if (lane == 0) { s0[0] = v0; s1[0] = v1; }
    }
    __syncthreads();
    v0 = s0[0]; v1 = s1[0];
}

// ---------------- f32 -> f16 convert, 6 segments in one launch ----------------
__device__ __forceinline__ void f2h8(const float* __restrict__ src, __half* __restrict__ dst,
                                     long long i)
{
    float4 a = *reinterpret_cast<const float4*>(src + i);
    float4 b = *reinterpret_cast<const float4*>(src + i + 4);
    __half2 h0 = __floats2half2_rn(a.x, a.y);
    __half2 h1 = __floats2half2_rn(a.z, a.w);
    __half2 h2 = __floats2half2_rn(b.x, b.y);
    __half2 h3 = __floats2half2_rn(b.z, b.w);
    uint4 u;
    u.x = *reinterpret_cast<uint32_t*>(&h0);
    u.y = *reinterpret_cast<uint32_t*>(&h1);
    u.z = *reinterpret_cast<uint32_t*>(&h2);
    u.w = *reinterpret_cast<uint32_t*>(&h3);
    *reinterpret_cast<uint4*>(dst + i) = u;
}

struct F2HSeg { const float* s; __half* d; long long n; };

__global__ __launch_bounds__(256)
void f2h6_kernel(F2HSeg a0, F2HSeg a1, F2HSeg a2, F2HSeg a3, F2HSeg a4, F2HSeg a5)
{
    long long i = ((long long)blockIdx.x * 256 + threadIdx.x) * 8;
    if (i < a0.n) { f2h8(a0.s, a0.d, i); return; }  i -= a0.n;
    if (i < a1.n) { f2h8(a1.s, a1.d, i); return; }  i -= a1.n;
    if (i < a2.n) { f2h8(a2.s, a2.d, i); return; }  i -= a2.n;
    if (i < a3.n) { f2h8(a3.s, a3.d, i); return; }  i -= a3.n;
    if (i < a4.n) { f2h8(a4.s, a4.d, i); return; }  i -= a4.n;
    if (i < a5.n) { f2h8(a5.s, a5.d, i); }
}

// ---------------- fp16 cp.async pipelined GEMM ----------------
// MODE 0: write fp32 C. MODE 1: split write Zh (col<2048, fp16) / Zt (tail fp32).
// MODE 2: resid add from R, write fp32 C + fp16 Ch.
#define TCG_STAGE 32768
#define TCG_SMEM  (3 * TCG_STAGE)

template<int MODE>
__global__ void __launch_bounds__(256, 2)
tc_gemm(const __half* __restrict__ A,
        const __half* __restrict__ W0, const __half* __restrict__ W1,
        const float* __restrict__ R, float* __restrict__ C, __half* __restrict__ Ch,
        int M, int N, int K)
{
    extern __shared__ uint32_t smem[];
    const uint32_t sb = smem_u32(smem);
    const int tid = threadIdx.x, wid = tid >> 5, lane = tid & 31;
    const int m0 = blockIdx.y * 128;
    const int n0 = blockIdx.x * 128;
    const __half* __restrict__ W = (m0 < BT) ? W0 : W1;

    const int wm = wid & 1;
    const int wn = wid >> 1;
    const int g  = lane >> 2;
    const int tg = lane & 3;
    const int lrow = lane & 15;
    const int lchi = lane >> 4;

    float acc[4][4][4];
    #pragma unroll
    for (int a = 0; a < 4; a++)
        #pragma unroll
        for (int b = 0; b < 4; b++)
            #pragma unroll
            for (int q = 0; q < 4; q++) acc[a][b][q] = 0.f;

    const int ntiles = K >> 6;

    auto issue_stage = [&](int i) {
        const uint32_t ab = sb + (i % 3) * TCG_STAGE;
        const uint32_t bb = ab + 16384;
        const __half* Ak = A + (size_t)m0 * K + i * 64;
        const __half* Wk = W + i * 64;
        #pragma unroll
        for (int j = 0; j < 4; j++) {
            int idx = tid + j * 256;
            int r = idx >> 3, ch = idx & 7;
            cp16(ab + SWZ((uint32_t)(r * 128 + ch * 16)), Ak + (size_t)r * K + ch * 8);
        }
        #pragma unroll
        for (int j = 0; j < 4; j++) {
            int idx = tid + j * 256;
            int r = idx >> 3, ch = idx & 7;
            int n = n0 + r; if (n >= N) n = N - 1;
            cp16(bb + SWZ((uint32_t)(r * 128 + ch * 16)), Wk + (size_t)n * K + ch * 8);
        }
        asm volatile("cp.async.commit_group;" ::: "memory");
    };

    issue_stage(0);
    issue_stage(1);

    for (int i = 0; i < ntiles; i++) {
        if (i + 1 < ntiles)
            asm volatile("cp.async.wait_group 1;" ::: "memory");
        else
            asm volatile("cp.async.wait_group 0;" ::: "memory");
        __syncthreads();
        if (i + 2 < ntiles) issue_stage(i + 2);

        const uint32_t ab = sb + (i % 3) * TCG_STAGE;
        const uint32_t bb = ab + 16384;

        uint32_t arow[4], arx[4];
        #pragma unroll
        for (int mi = 0; mi < 4; mi++) {
            int r = wm * 64 + mi * 16 + lrow;
            arow[mi] = ab + (uint32_t)r * 128;
            arx[mi] = (uint32_t)(r & 7);
        }
        uint32_t brow[2], brx[2];
        #pragma unroll
        for (int nj = 0; nj < 2; nj++) {
            int r = wn * 32 + nj * 16 + lrow;
            brow[nj] = bb + (uint32_t)r * 128;
            brx[nj] = (uint32_t)(r & 7);
        }

        #pragma unroll
        for (int ks = 0; ks < 4; ks++) {
            const uint32_t ch = (uint32_t)(2 * ks + lchi);
            uint32_t af[4][4];
            #pragma unroll
            for (int mi = 0; mi < 4; mi++) {
                uint32_t addr = arow[mi] + ((ch ^ arx[mi]) << 4);
                asm volatile("ldmatrix.sync.aligned.m8n8.x4.shared.b16 {%0,%1,%2,%3}, [%4];"
                             : "=r"(af[mi][0]), "=r"(af[mi][1]), "=r"(af[mi][2]), "=r"(af[mi][3])
                             : "r"(addr));
            }
            uint32_t bf[4][2];
            #pragma unroll
            for (int nj = 0; nj < 2; nj++) {
                uint32_t addr = brow[nj] + ((ch ^ brx[nj]) << 4);
                uint32_t r0, r1, r2, r3;
                asm volatile("ldmatrix.sync.aligned.m8n8.x4.shared.b16 {%0,%1,%2,%3}, [%4];"
                             : "=r"(r0), "=r"(r1), "=r"(r2), "=r"(r3) : "r"(addr));
                bf[nj * 2 + 0][0] = r0; bf[nj * 2 + 0][1] = r2;
                bf[nj * 2 + 1][0] = r1; bf[nj * 2 + 1][1] = r3;
            }
            #pragma unroll
            for (int mi = 0; mi < 4; mi++)
                #pragma unroll
                for (int ni = 0; ni < 4; ni++) {
                    asm volatile(
                        "mma.sync.aligned.m16n8k16.row.col.f32.f16.f16.f32 "
                        "{%0,%1,%2,%3}, {%4,%5,%6,%7}, {%8,%9}, {%0,%1,%2,%3};"
                        : "+f"(acc[mi][ni][0]), "+f"(acc[mi][ni][1]),
                          "+f"(acc[mi][ni][2]), "+f"(acc[mi][ni][3])
                        : "r"(af[mi][0]), "r"(af[mi][1]), "r"(af[mi][2]), "r"(af[mi][3]),
                          "r"(bf[ni][0]), "r"(bf[ni][1]));
                }
        }
        __syncthreads();
    }

    #pragma unroll
    for (int mi = 0; mi < 4; mi++) {
        #pragma unroll
        for (int ni = 0; ni < 4; ni++) {
            int row = m0 + wm * 64 + mi * 16 + g;
            int col = n0 + wn * 32 + ni * 8 + tg * 2;
            if (col >= N) continue;
            float2 v0 = make_float2(acc[mi][ni][0], acc[mi][ni][1]);
            float2 v1 = make_float2(acc[mi][ni][2], acc[mi][ni][3]);
            if (MODE == 0) {
                *reinterpret_cast<float2*>(&C[(size_t)row * N + col]) = v0;
                *reinterpret_cast<float2*>(&C[(size_t)(row + 8) * N + col]) = v1;
            } else if (MODE == 1) {
                if (col < ZH_COLS) {
                    *reinterpret_cast<__half2*>(&Ch[(size_t)row * ZH_COLS + col]) =
                        __floats2half2_rn(v0.x, v0.y);
                    *reinterpret_cast<__half2*>(&Ch[(size_t)(row + 8) * ZH_COLS + col]) =
                        __floats2half2_rn(v1.x, v1.y);
                } else {
                    int tc = col - ZH_COLS;
                    *reinterpret_cast<float2*>(&C[(size_t)row * ZT_COLS + tc]) = v0;
                    *reinterpret_cast<float2*>(&C[(size_t)(row + 8) * ZT_COLS + tc]) = v1;
                }
            } else {
                size_t o0 = (size_t)row * N + col;
                size_t o1 = (size_t)(row + 8) * N + col;
                float2 r0 = *reinterpret_cast<const float2*>(&R[o0]);
                float2 r1 = *reinterpret_cast<const float2*>(&R[o1]);
                v0.x += r0.x; v0.y += r0.y;
                v1.x += r1.x; v1.y += r1.y;
                *reinterpret_cast<float2*>(&C[o0]) = v0;
                *reinterpret_cast<float2*>(&C[o1]) = v1;
                *reinterpret_cast<__half2*>(&Ch[o0]) = __floats2half2_rn(v0.x, v0.y);
                *reinterpret_cast<__half2*>(&Ch[o1]) = __floats2half2_rn(v1.x, v1.y);
            }
        }
    }
}

// ---------------- embed LN ----------------
__global__ __launch_bounds__(256)
void ln1_kernel(const float* __restrict__ tmp, const float* __restrict__ eb,
                const float* __restrict__ w, const float* __restrict__ bias,
                float* __restrict__ H, __half* __restrict__ Hh)
{
    int row = blockIdx.x;
    int b = row / TLEN, t = row % TLEN;
    const float* src = tmp + (size_t)row * D_MODEL;
    float v[2]; float s = 0.f, ss = 0.f;
    #pragma unroll
    for (int i = 0; i < 2; i++) {
        int j = threadIdx.x + i * 256;
        float val = src[j] + eb[j];
        v[i] = val; s += val; ss += val * val;
    }
    block_reduce2(s, ss);
    float m = s * (1.f / D_MODEL);
    float var = fmaxf(ss * (1.f / D_MODEL) - m * m, 0.f);
    float inv = rsqrtf(var + LN_EPS);
    size_t rf = ((size_t)b * TLEN + t) * D_MODEL;
    size_t rb = ((size_t)(BATCH + b) * TLEN + (TLEN - 1 - t)) * D_MODEL;
    #pragma unroll
    for (int i = 0; i < 2; i++) {
        int j = threadIdx.x + i * 256;
        float o = (v[i] - m) * inv * w[j] + bias[j];
        H[rf + j] = o;  H[rb + j] = o;
        __half oh = __float2half_rn(o);
        Hh[rf + j] = oh; Hh[rb + j] = oh;
    }
}

// ---------------- conv over B/C columns only + dt/dA tail (reads fp32 Zt) ----------------
__global__ __launch_bounds__(256)
void conv_bc_kernel(const float* __restrict__ Zt,
                    const float* __restrict__ cw0, const float* __restrict__ cw1,
                    const float* __restrict__ cb0, const float* __restrict__ cb1,
                    const float* __restrict__ db0, const float* __restrict__ db1,
                    const float* __restrict__ al0, const float* __restrict__ al1,
                    float* __restrict__ BC, float* __restrict__ dA, float* __restrict__ dt)
{
    long long idx = (long long)blockIdx.x * blockDim.x + threadIdx.x;
    const long long NBC = (long long)GBT * 2 * DSTATE;
    if (idx < NBC) {
        int n = (int)(idx % (2 * DSTATE));
        int gt = (int)(idx / (2 * DSTATE));
        int t = gt % TLEN;
        bool back = gt >= BT;
        int c = D_INNER + n;
        const float* cw = back ? cw1 : cw0;
        const float* cb = back ? cb1 : cb0;
        float acc = cb[c];
        #pragma unroll
        for (int j = 0; j < DCONV; j++) {
            int tt = t - (DCONV - 1) + j;
            if (tt >= 0)
                acc = fmaf(cw[c * DCONV + j],
                           Zt[(size_t)(gt - (DCONV - 1) + j) * ZT_COLS + n], acc);
        }
        BC[idx] = siluf(acc);
    } else {
        long long j = idx - NBC;
        if (j >= (long long)GBT * NHEADS) return;
        int h = (int)(j % NHEADS);
        int row = (int)(j / NHEADS);
        bool back = row >= BT;
        float raw = Zt[(size_t)row * ZT_COLS + 2 * DSTATE + h] + (back ? db1 : db0)[h];
        float d = softplusf(raw);
        float Av = expf((back ? al1 : al0)[h]);
        dt[j] = d;
        dA[j] = expf(-Av * d);
    }
}

// ---------------- two-pass chunked selective scan (x from fp16 Zh) ----------------
struct SDR { float z, a, dt; float bb[DSTATE]; float cc[DSTATE]; };
struct SDB { float z, a, dt; float bb[DSTATE]; };

__device__ __forceinline__ SDR load_raw(const __half* __restrict__ Zx,
                                        const float* __restrict__ BC,
                                        const float* __restrict__ dA,
                                        const float* __restrict__ dtv,
                                        size_t row)
{
    SDR d;
    d.z = __half2float(Zx[row * ZH_COLS]);
    const float4* bp = reinterpret_cast<const float4*>(BC + row * 2 * DSTATE);
    #pragma unroll
    for (int i = 0; i < 4; i++) {
        float4 b = bp[i];
        d.bb[4 * i + 0] = b.x; d.bb[4 * i + 1] = b.y; d.bb[4 * i + 2] = b.z; d.bb[4 * i + 3] = b.w;
        float4 c = bp[4 + i];
        d.cc[4 * i + 0] = c.x; d.cc[4 * i + 1] = c.y; d.cc[4 * i + 2] = c.z; d.cc[4 * i + 3] = c.w;
    }
    d.a  = dA[row * NHEADS];
    d.dt = dtv[row * NHEADS];
    return d;
}

__device__ __forceinline__ SDB load_rawB(const __half* __restrict__ Zx,
                                         const float* __restrict__ BC,
                                         const float* __restrict__ dA,
                                         const float* __restrict__ dtv,
                                         size_t row)
{
    SDB d;
    d.z = __half2float(Zx[row * ZH_COLS]);
    const float4* bp = reinterpret_cast<const float4*>(BC + row * 2 * DSTATE);
    #pragma unroll
    for (int i = 0; i < 4; i++) {
        float4 b = bp[i];
        d.bb[4 * i + 0] = b.x; d.bb[4 * i + 1] = b.y; d.bb[4 * i + 2] = b.z; d.bb[4 * i + 3] = b.w;
    }
    d.a  = dA[row * NHEADS];
    d.dt = dtv[row * NHEADS];
    return d;
}

__device__ __forceinline__ float scan_step_x(float s[DSTATE], const SDR& d, float xs, float Dv)
{
    float xdt = xs * d.dt;
    float y0 = 0.f, y1 = 0.f, y2 = 0.f, y3 = 0.f;
    #pragma unroll
    for (int n = 0; n < DSTATE; n += 4) {
        s[n + 0] = fmaf(d.a, s[n + 0], xdt * d.bb[n + 0]); y0 = fmaf(s[n + 0], d.cc[n + 0], y0);
        s[n + 1] = fmaf(d.a, s[n + 1], xdt * d.bb[n + 1]); y1 = fmaf(s[n + 1], d.cc[n + 1], y1);
        s[n + 2] = fmaf(d.a, s[n + 2], xdt * d.bb[n + 2]); y2 = fmaf(s[n + 2], d.cc[n + 2], y2);
        s[n + 3] = fmaf(d.a, s[n + 3], xdt * d.bb[n + 3]); y3 = fmaf(s[n + 3], d.cc[n + 3], y3);
    }
    return (y0 + y1) + (y2 + y3) + Dv * xs;
}

__device__ __forceinline__ void state_step(float s[DSTATE], const SDB& d, float xs)
{
    float xdt = xs * d.dt;
    #pragma unroll
    for (int n = 0; n < DSTATE; n++)
        s[n] = fmaf(d.a, s[n], xdt * d.bb[n]);
}

#define CONV_STEP(zin, xs_out)                                                            \
    float xs_out = siluf(fmaf(cwv.w, (zin), fmaf(cwv.z, w2, fmaf(cwv.y, w1, fmaf(cwv.x, w0, cbv))))); \
    w0 = w1; w1 = w2; w2 = (zin);

// pass 1: state-only per-chunk scan from zero state -> E, Pf
__global__ __launch_bounds__(HEADDIM)
void scan_pass1(const __half* __restrict__ Zh, const float* __restrict__ BC,
                const float* __restrict__ dA, const float* __restrict__ dtv,
                const float* __restrict__ cw0, const float* __restrict__ cw1,
                const float* __restrict__ cb0, const float* __restrict__ cb1,
                float* __restrict__ E, float* __restrict__ Pf)
{
    int bc = blockIdx.x;
    int gh = bc / NCH, c = bc % NCH;
    int g = gh / NHEADS, h = gh % NHEADS;
    int p = threadIdx.x;
    bool back = g >= BATCH;
    size_t rowB = (size_t)g * TLEN + (size_t)c * CHUNK;
    int hp = h * HEADDIM + p;

    const float4 cwv = *reinterpret_cast<const float4*>((back ? cw1 : cw0) + hp * DCONV);
    const float cbv = (back ? cb1 : cb0)[hp];
    const __half* Zx = Zh + D_INNER + hp;

    float w0 = 0.f, w1 = 0.f, w2 = 0.f;
    if (c > 0) {
        w0 = __half2float(Zx[(rowB - 3) * ZH_COLS]);
        w1 = __half2float(Zx[(rowB - 2) * ZH_COLS]);
        w2 = __half2float(Zx[(rowB - 1) * ZH_COLS]);
    }

    const float* dAh = dA + h;
    const float* dth = dtv + h;

    float s[DSTATE];
    #pragma unroll
    for (int n = 0; n < DSTATE; n++) s[n] = 0.f;
    float P = 1.f;

    SDB a = load_rawB(Zx, BC, dAh, dth, rowB + 0);
    SDB b = load_rawB(Zx, BC, dAh, dth, rowB + 1);
    for (int t = 0; t < CHUNK; t += 4) {
        SDB cc = load_rawB(Zx, BC, dAh, dth, rowB + t + 2);
        SDB dd = load_rawB(Zx, BC, dAh, dth, rowB + t + 3);
        { CONV_STEP(a.z, xs); state_step(s, a, xs); P *= a.a; }
        { CONV_STEP(b.z, xs); state_step(s, b, xs); P *= b.a; }
        if (t + 4 < CHUNK) {
            a = load_rawB(Zx, BC, dAh, dth, rowB + t + 4);
            b = load_rawB(Zx, BC, dAh, dth, rowB + t + 5);
        }
        { CONV_STEP(cc.z, xs); state_step(s, cc, xs); P *= cc.a; }
        { CONV_STEP(dd.z, xs); state_step(s, dd, xs); P *= dd.a; }
    }

    float4* Ep = reinterpret_cast<float4*>(E + ((size_t)bc * HEADDIM + p) * DSTATE);
    #pragma unroll
    for (int i = 0; i < 4; i++)
        Ep[i] = make_float4(s[4*i], s[4*i+1], s[4*i+2], s[4*i+3]);
    if (p == 0) Pf[bc] = P;
}

// phase 2: sequential chunk-state recurrence per (g,h)
__global__ __launch_bounds__(HEADDIM)
void scan2_kernel(const float* __restrict__ E, const float* __restrict__ Pf,
                  float* __restrict__ S0)
{
    int gh = blockIdx.x;
    int p = threadIdx.x;
    float s0[DSTATE];
    #pragma unroll
    for (int n = 0; n < DSTATE; n++) s0[n] = 0.f;

    for (int c = 0; c < NCH; c++) {
        size_t base = (((size_t)gh * NCH + c) * HEADDIM + p) * DSTATE;
        float4* So = reinterpret_cast<float4*>(S0 + base);
        #pragma unroll
        for (int i = 0; i < 4; i++)
            So[i] = make_float4(s0[4*i], s0[4*i+1], s0[4*i+2], s0[4*i+3]);
        float Pc = Pf[gh * NCH + c];
        const float4* Ep = reinterpret_cast<const float4*>(E + base);
        #pragma unroll
        for (int i = 0; i < 4; i++) {
            float4 e = Ep[i];
            s0[4*i+0] = fmaf(Pc, s0[4*i+0], e.x);
            s0[4*i+1] = fmaf(Pc, s0[4*i+1], e.y);
            s0[4*i+2] = fmaf(Pc, s0[4*i+2], e.z);
            s0[4*i+3] = fmaf(Pc, s0[4*i+3], e.w);
        }
    }
}

// pass 2: full local scan initialized with s0; writes final Y (fp16) once
__global__ __launch_bounds__(HEADDIM)
void scan_pass2(const __half* __restrict__ Zh, const float* __restrict__ BC,
                const float* __restrict__ dA, const float* __restrict__ dtv,
                const float* __restrict__ cw0, const float* __restrict__ cw1,
                const float* __restrict__ cb0, const float* __restrict__ cb1,
                const float* __restrict__ D0, const float* __restrict__ D1,
                const float* __restrict__ S0, __half* __restrict__ Y)
{
    int bc = blockIdx.x;
    int gh = bc / NCH, c = bc % NCH;
    int g = gh / NHEADS, h = gh % NHEADS;
    int p = threadIdx.x;
    bool back = g >= BATCH;
    float Dv = (back ? D1 : D0)[h];
    size_t rowB = (size_t)g * TLEN + (size_t)c * CHUNK;
    int hp = h * HEADDIM + p;

    const float4 cwv = *reinterpret_cast<const float4*>((back ? cw1 : cw0) + hp * DCONV);
    const float cbv = (back ? cb1 : cb0)[hp];
    const __half* Zx = Zh + D_INNER + hp;

    float w0 = 0.f, w1 = 0.f, w2 = 0.f;
    if (c > 0) {
        w0 = __half2float(Zx[(rowB - 3) * ZH_COLS]);
        w1 = __half2float(Zx[(rowB - 2) * ZH_COLS]);
        w2 = __half2float(Zx[(rowB - 1) * ZH_COLS]);
    }

    const float* dAh = dA + h;
    const float* dth = dtv + h;

    float s[DSTATE];
    {
        const float4* So = reinterpret_cast<const float4*>(
            S0 + ((size_t)bc * HEADDIM + p) * DSTATE);
        #pragma unroll
        for (int i = 0; i < 4; i++) {
            float4 v = So[i];
            s[4*i] = v.x; s[4*i+1] = v.y; s[4*i+2] = v.z; s[4*i+3] = v.w;
        }
    }

    SDR a = load_raw(Zx, BC, dAh, dth, rowB + 0);
    SDR b = load_raw(Zx, BC, dAh, dth, rowB + 1);
    for (int t = 0; t < CHUNK; t += 4) {
        SDR cc = load_raw(Zx, BC, dAh, dth, rowB + t + 2);
        SDR dd = load_raw(Zx, BC, dAh, dth, rowB + t + 3);
        { CONV_STEP(a.z, xs); Y[(rowB + t + 0) * D_INNER + hp] = __float2half_rn(scan_step_x(s, a, xs, Dv)); }
        { CONV_STEP(b.z, xs); Y[(rowB + t + 1) * D_INNER + hp] = __float2half_rn(scan_step_x(s, b, xs, Dv)); }
        if (t + 4 < CHUNK) {
            a = load_raw(Zx, BC, dAh, dth, rowB + t + 4);
            b = load_raw(Zx, BC, dAh, dth, rowB + t + 5);
        }
        { CONV_STEP(cc.z, xs); Y[(rowB + t + 2) * D_INNER + hp] = __float2half_rn(scan_step_x(s, cc, xs, Dv)); }
        { CONV_STEP(dd.z, xs); Y[(rowB + t + 3) * D_INNER + hp] = __float2half_rn(scan_step_x(s, dd, xs, Dv)); }
    }
}

// ---------------- gate + RMSNorm -> fp16 G (reads fp16 Y + fp16 z) ----------------
__global__ __launch_bounds__(256)
void gate_rms_kernel(const __half* __restrict__ Zh, const __half* __restrict__ Y,
                     __half* __restrict__ Gh,
                     const float* __restrict__ rw0, const float* __restrict__ rw1)
{
    int row = blockIdx.x;
    const float* rw = (row < BT) ? rw0 : rw1;
    const __half* zr = Zh + (size_t)row * ZH_COLS;
    const __half* yr = Y + (size_t)row * D_INNER;
    __half* go = Gh + (size_t)row * D_INNER;
    float v[4]; float ss = 0.f;
    #pragma unroll
    for (int i = 0; i < 4; i++) {
        int j = threadIdx.x + i * 256;
        float gv = __half2float(yr[j]) * siluf(__half2float(zr[j]));
        v[i] = gv; ss += gv * gv;
    }
    float dummy = 0.f;
    block_reduce2(ss, dummy);
    float inv = rsqrtf(ss * (1.f / D_INNER) + LN_EPS);
    #pragma unroll
    for (int i = 0; i < 4; i++) {
        int j = threadIdx.x + i * 256;
        go[j] = __float2half_rn(v[i] * inv * rw[j]);
    }
}

// ---------------- final concat + layernorm ----------------
__global__ __launch_bounds__(256)
void final_kernel(const float* __restrict__ H, const float* __restrict__ w,
                  const float* __restrict__ bias, float* __restrict__ out)
{
    int row = blockIdx.x;
    int b = row / TLEN, t = row % TLEN;
    const float* hf = H + ((size_t)b * TLEN + t) * D_MODEL;
    const float* hb = H + ((size_t)(BATCH + b) * TLEN + (TLEN - 1 - t)) * D_MODEL;
    float v[4]; float s = 0.f, ss = 0.f;
    #pragma unroll
    for (int i = 0; i < 4; i++) {
        int j = threadIdx.x + i * 256;
        float val = (i < 2) ? hf[j] : hb[j - D_MODEL];
        v[i] = val; s += val; ss += val * val;
    }
    block_reduce2(s, ss);
    const float invN = 1.f / (2 * D_MODEL);
    float m = s * invN;
    float var = fmaxf(ss * invN - m * m, 0.f);
    float inv = rsqrtf(var + LN_EPS);
    float* o = out + (size_t)row * (2 * D_MODEL);
    #pragma unroll
    for (int i = 0; i < 4; i++) {
        int j = threadIdx.x + i * 256;
        o[j] = (v[i] - m) * inv * w[j] + bias[j];
    }
}

// ---------------- launcher ----------------
extern "C" void kernel_launch(void* const* d_in, const int* in_sizes, int n_in,
                              void* d_out, int out_size)
{
    const float* x        = (const float*)d_in[0];
    const float* embed_w  = (const float*)d_in[1];
    const float* embed_b  = (const float*)d_in[2];
    const float* ln1_w    = (const float*)d_in[3];
    const float* ln1_b    = (const float*)d_in[4];
    const float* lnout_w  = (const float*)d_in[5];
    const float* lnout_b  = (const float*)d_in[6];
    const float* in_w[2]    = {(const float*)d_in[7],  (const float*)d_in[15]};
    const float* conv_w[2]  = {(const float*)d_in[8],  (const float*)d_in[16]};
    const float* conv_b[2]  = {(const float*)d_in[9],  (const float*)d_in[17]};
    const float* dt_bias[2] = {(const float*)d_in[10], (const float*)d_in[18]};
    const float* A_log[2]   = {(const float*)d_in[11], (const float*)d_in[19]};
    const float* Dp[2]      = {(const float*)d_in[12], (const float*)d_in[20]};
    const float* rms_w[2]   = {(const float*)d_in[13], (const float*)d_in[21]};
    const float* out_w[2]   = {(const float*)d_in[14], (const float*)d_in[22]};
    float* out = (float*)d_out;

    float *pH, *pZt, *pBC, *pdA, *pdt, *ptmp, *pE, *pS0, *pPf;
    __half *pHh, *pZh, *pYh, *pGh, *pxh, *pewh, *piwh, *powh;
    cudaGetSymbolAddress((void**)&pH,   g_H);
    cudaGetSymbolAddress((void**)&pHh,  g_Hh);
    cudaGetSymbolAddress((void**)&pZh,  g_Zh);
    cudaGetSymbolAddress((void**)&pZt,  g_Zt);
    cudaGetSymbolAddress((void**)&pBC,  g_BC);
    cudaGetSymbolAddress((void**)&pdA,  g_dA);
    cudaGetSymbolAddress((void**)&pdt,  g_dt);
    cudaGetSymbolAddress((void**)&pYh,  g_Yh);
    cudaGetSymbolAddress((void**)&pGh,  g_Gh);
    cudaGetSymbolAddress((void**)&ptmp, g_tmp);
    cudaGetSymbolAddress((void**)&pxh,  g_xh);
    cudaGetSymbolAddress((void**)&pewh, g_ewh);
    cudaGetSymbolAddress((void**)&piwh, g_iwh);
    cudaGetSymbolAddress((void**)&powh, g_owh);
    cudaGetSymbolAddress((void**)&pE,   g_E);
    cudaGetSymbolAddress((void**)&pS0,  g_S0);
    cudaGetSymbolAddress((void**)&pPf,  g_Pf);

    cudaFuncSetAttribute(tc_gemm<0>, cudaFuncAttributeMaxDynamicSharedMemorySize, TCG_SMEM);
    cudaFuncSetAttribute(tc_gemm<1>, cudaFuncAttributeMaxDynamicSharedMemorySize, TCG_SMEM);
    cudaFuncSetAttribute(tc_gemm<2>, cudaFuncAttributeMaxDynamicSharedMemorySize, TCG_SMEM);

    const size_t IWSZ = (size_t)NLAYERS * D_IN_PROJ * D_MODEL;
    const size_t OWSZ = (size_t)NLAYERS * D_MODEL * D_INNER;

    {
        F2HSeg s0 = { x,        pxh,         (long long)BT * INPUT_DIM };
        F2HSeg s1 = { embed_w,  pewh,        (long long)D_MODEL * INPUT_DIM };
        F2HSeg s2 = { in_w[0],  piwh,        (long long)IWSZ };
        F2HSeg s3 = { in_w[1],  piwh + IWSZ, (long long)IWSZ };
        F2HSeg s4 = { out_w[0], powh,        (long long)OWSZ };
        F2HSeg s5 = { out_w[1], powh + OWSZ, (long long)OWSZ };
        long long total = s0.n + s1.n + s2.n + s3.n + s4.n + s5.n;
        f2h6_kernel<<<(unsigned)((total / 8 + 255) / 256), 256>>>(s0, s1, s2, s3, s4, s5);
    }

    tc_gemm<0><<<dim3(D_MODEL / 128, BT / 128), 256, TCG_SMEM>>>(
        pxh, pewh, pewh, nullptr, ptmp, nullptr, BT, D_MODEL, INPUT_DIM);
    ln1_kernel<<<BT, 256>>>(ptmp, embed_b, ln1_w, ln1_b, pH, pHh);

    for (int L = 0; L < NLAYERS; L++) {
        const __half* iw0 = piwh + (size_t)L * D_IN_PROJ * D_MODEL;
        const __half* iw1 = piwh + IWSZ + (size_t)L * D_IN_PROJ * D_MODEL;
        const __half* ow0 = powh + (size_t)L * D_MODEL * D_INNER;
        const __half* ow1 = powh + OWSZ + (size_t)L * D_MODEL * D_INNER;
        const float* cw0 = conv_w[0] + (size_t)L * CONV_DIM * DCONV;
        const float* cw1 = conv_w[1] + (size_t)L * CONV_DIM * DCONV;
        const float* cb0 = conv_b[0] + (size_t)L * CONV_DIM;
        const float* cb1 = conv_b[1] + (size_t)L * CONV_DIM;
        const float* db0 = dt_bias[0] + L * NHEADS;
        const float* db1 = dt_bias[1] + L * NHEADS;
        const float* al0 = A_log[0] + L * NHEADS;
        const float* al1 = A_log[1] + L * NHEADS;
        const float* D0  = Dp[0] + L * NHEADS;
        const float* D1  = Dp[1] + L * NHEADS;
        const float* rw0 = rms_w[0] + (size_t)L * D_INNER;
        const float* rw1 = rms_w[1] + (size_t)L * D_INNER;

        tc_gemm<1><<<dim3((D_IN_PROJ + 127) / 128, GBT / 128), 256, TCG_SMEM>>>(
            pHh, iw0, iw1, nullptr, pZt, pZh, GBT, D_IN_PROJ, D_MODEL);

        {
            long long total = (long long)GBT * 2 * DSTATE + (long long)GBT * NHEADS;
            conv_bc_kernel<<<(unsigned)((total + 255) / 256), 256>>>(
                pZt, cw0, cw1, cb0, cb1, db0, db1, al0, al1, pBC, pdA, pdt);
        }

        scan_pass1<<<GB * NHEADS * NCH, HEADDIM>>>(
            pZh, pBC, pdA, pdt, cw0, cw1, cb0, cb1, pE, pPf);
        scan2_kernel<<<GB * NHEADS, HEADDIM>>>(pE, pPf, pS0);
        scan_pass2<<<GB * NHEADS * NCH, HEADDIM>>>(
            pZh, pBC, pdA, pdt, cw0, cw1, cb0, cb1, D0, D1, pS0, pYh);

        gate_rms_kernel<<<GBT, 256>>>(pZh, pYh, pGh, rw0, rw1);

        tc_gemm<2><<<dim3(D_MODEL / 128, GBT / 128), 256, TCG_SMEM>>>(
            pGh, ow0, ow1, pH, pH, pHh, GBT, D_MODEL, D_INNER);
    }

    final_kernel<<<BT, 256>>>(pH, lnout_w, lnout_b, out);
}

// round 17
// speedup vs baseline: 1.2217x; 1.2217x over previous
#include <cuda_runtime.h>
#include <cuda_fp16.h>
#include <stdint.h>
#include <math.h>

#define BATCH 4
#define TLEN 2048
#define INPUT_DIM 256
#define D_MODEL 512
#define D_INNER 1024
#define NHEADS 8
#define HEADDIM 128
#define DSTATE 16
#define DCONV 4
#define CONV_DIM (D_INNER + 2*DSTATE)                 // 1056
#define D_IN_PROJ (2*D_INNER + 2*DSTATE + NHEADS)     // 2088
#define NLAYERS 4
#define GB (2*BATCH)          // 8
#define BT (BATCH*TLEN)       // 8192
#define GBT (GB*TLEN)         // 16384
#define LN_EPS 1e-5f
#define CHUNK 128
#define NCH (TLEN / CHUNK)    // 16
#define NCH1 (NCH - 1)        // pass1 chunks per (g,h)

// ---------------- scratch ----------------
__device__ __align__(128) float  g_H  [(size_t)GBT * D_MODEL];
__device__ __align__(128) __half g_Hh [(size_t)GBT * D_MODEL];
__device__ __align__(128) float  g_Z  [(size_t)GBT * D_IN_PROJ];
__device__ __align__(128) float  g_BC [(size_t)GBT * 2 * DSTATE];
__device__ __align__(128) float  g_dA [(size_t)GBT * NHEADS];
__device__ __align__(128) float  g_dt [(size_t)GBT * NHEADS];
__device__ __align__(128) __half g_Yh [(size_t)GBT * D_INNER];
__device__ __align__(128) __half g_Gh [(size_t)GBT * D_INNER];
__device__ __align__(128) float  g_tmp[(size_t)BT  * D_MODEL];
__device__ __align__(128) __half g_xh [(size_t)BT * INPUT_DIM];
__device__ __align__(128) __half g_ewh[(size_t)D_MODEL * INPUT_DIM];
__device__ __align__(128) __half g_iwh[(size_t)2 * NLAYERS * D_IN_PROJ * D_MODEL];
__device__ __align__(128) __half g_owh[(size_t)2 * NLAYERS * D_MODEL * D_INNER];
// chunked-scan scratch
__device__ __align__(128) float  g_E [(size_t)GB * NHEADS * NCH * HEADDIM * DSTATE];
__device__ __align__(128) float  g_S0[(size_t)GB * NHEADS * NCH * HEADDIM * DSTATE];
__device__ __align__(128) float  g_Pf[GB * NHEADS * NCH];

// ---------------- helpers ----------------
__device__ __forceinline__ float siluf(float v) { return v / (1.f + expf(-v)); }
__device__ __forceinline__ float softplusf(float v) { return v > 20.f ? v : log1pf(expf(v)); }

__device__ __forceinline__ uint32_t smem_u32(const void* p) {
    uint32_t a;
    asm("{ .reg .u64 t; cvta.to.shared.u64 t, %1; cvt.u32.u64 %0, t; }" : "=r"(a) : "l"(p));
    return a;
}
__device__ __forceinline__ void cp16(uint32_t dst, const void* src) {
    asm volatile("cp.async.cg.shared.global [%0], [%1], 16;" :: "r"(dst), "l"(src) : "memory");
}
#define SWZ(off) ((off) ^ (((off) >> 3) & 0x70))

__device__ __forceinline__ void block_reduce2(float& v0, float& v1)
{
    __shared__ float s0[32], s1[32];
    int lane = threadIdx.x & 31, wid = threadIdx.x >> 5;
    #pragma unroll
    for (int o = 16; o > 0; o >>= 1) {
        v0 += __shfl_xor_sync(0xffffffffu, v0, o);
        v1 += __shfl_xor_sync(0xffffffffu, v1, o);
    }
    if (lane == 0) { s0[wid] = v0; s1[wid] = v1; }
    __syncthreads();
    int nw = blockDim.x >> 5;
    if (wid == 0) {
        v0 = (lane < nw) ? s0[lane] : 0.f;
        v1 = (lane < nw) ? s1[lane] : 0.f;
        #pragma unroll
        for (int o = 16; o > 0; o >>= 1) {
            v0 += __shfl_xor_sync(0xffffffffu, v0, o);
            v1 += __shfl_xor_sync(0xffffffffu, v1, o);
        }
        if (lane == 0) { s0[0] = v0; s1[0] = v1; }
    }
    __syncthreads();
    v0 = s0[0]; v1 = s1[0];
}

// ---------------- f32 -> f16 convert, 6 segments in one launch ----------------
__device__ __forceinline__ void f2h8(const float* __restrict__ src, __half* __restrict__ dst,
                                     long long i)
{
    float4 a = *reinterpret_cast<const float4*>(src + i);
    float4 b = *reinterpret_cast<const float4*>(src + i + 4);
    __half2 h0 = __floats2half2_rn(a.x, a.y);
    __half2 h1 = __floats2half2_rn(a.z, a.w);
    __half2 h2 = __floats2half2_rn(b.x, b.y);
    __half2 h3 = __floats2half2_rn(b.z, b.w);
    uint4 u;
    u.x = *reinterpret_cast<uint32_t*>(&h0);
    u.y = *reinterpret_cast<uint32_t*>(&h1);
    u.z = *reinterpret_cast<uint32_t*>(&h2);
    u.w = *reinterpret_cast<uint32_t*>(&h3);
    *reinterpret_cast<uint4*>(dst + i) = u;
}

struct F2HSeg { const float* s; __half* d; long long n; };

__global__ __launch_bounds__(256)
void f2h6_kernel(F2HSeg a0, F2HSeg a1, F2HSeg a2, F2HSeg a3, F2HSeg a4, F2HSeg a5)
{
    long long i = ((long long)blockIdx.x * 256 + threadIdx.x) * 8;
    if (i < a0.n) { f2h8(a0.s, a0.d, i); return; }  i -= a0.n;
    if (i < a1.n) { f2h8(a1.s, a1.d, i); return; }  i -= a1.n;
    if (i < a2.n) { f2h8(a2.s, a2.d, i); return; }  i -= a2.n;
    if (i < a3.n) { f2h8(a3.s, a3.d, i); return; }  i -= a3.n;
    if (i < a4.n) { f2h8(a4.s, a4.d, i); return; }  i -= a4.n;
    if (i < a5.n) { f2h8(a5.s, a5.d, i); }
}

// ---------------- fp16 cp.async pipelined GEMM ----------------
#define TCG_STAGE 32768
#define TCG_SMEM  (3 * TCG_STAGE)

template<bool RESID, bool HOUT>
__global__ void __launch_bounds__(256, 2)
tc_gemm(const __half* __restrict__ A,
        const __half* __restrict__ W0, const __half* __restrict__ W1,
        const float* __restrict__ R, float* __restrict__ C, __half* __restrict__ Ch,
        int M, int N, int K)
{
    extern __shared__ uint32_t smem[];
    const uint32_t sb = smem_u32(smem);
    const int tid = threadIdx.x, wid = tid >> 5, lane = tid & 31;
    const int m0 = blockIdx.y * 128;
    const int n0 = blockIdx.x * 128;
    const __half* __restrict__ W = (m0 < BT) ? W0 : W1;

    const int wm = wid & 1;
    const int wn = wid >> 1;
    const int g  = lane >> 2;
    const int tg = lane & 3;
    const int lrow = lane & 15;
    const int lchi = lane >> 4;

    float acc[4][4][4];
    #pragma unroll
    for (int a = 0; a < 4; a++)
        #pragma unroll
        for (int b = 0; b < 4; b++)
            #pragma unroll
            for (int q = 0; q < 4; q++) acc[a][b][q] = 0.f;

    const int ntiles = K >> 6;

    auto issue_stage = [&](int i) {
        const uint32_t ab = sb + (i % 3) * TCG_STAGE;
        const uint32_t bb = ab + 16384;
        const __half* Ak = A + (size_t)m0 * K + i * 64;
        const __half* Wk = W + i * 64;
        #pragma unroll
        for (int j = 0; j < 4; j++) {
            int idx = tid + j * 256;
            int r = idx >> 3, ch = idx & 7;
            cp16(ab + SWZ((uint32_t)(r * 128 + ch * 16)), Ak + (size_t)r * K + ch * 8);
        }
        #pragma unroll
        for (int j = 0; j < 4; j++) {
            int idx = tid + j * 256;
            int r = idx >> 3, ch = idx & 7;
            int n = n0 + r; if (n >= N) n = N - 1;
            cp16(bb + SWZ((uint32_t)(r * 128 + ch * 16)), Wk + (size_t)n * K + ch * 8);
        }
        asm volatile("cp.async.commit_group;" ::: "memory");
    };

    issue_stage(0);
    issue_stage(1);

    for (int i = 0; i < ntiles; i++) {
        if (i + 1 < ntiles)
            asm volatile("cp.async.wait_group 1;" ::: "memory");
        else
            asm volatile("cp.async.wait_group 0;" ::: "memory");
        __syncthreads();
        if (i + 2 < ntiles) issue_stage(i + 2);

        const uint32_t ab = sb + (i % 3) * TCG_STAGE;
        const uint32_t bb = ab + 16384;

        uint32_t arow[4], arx[4];
        #pragma unroll
        for (int mi = 0; mi < 4; mi++) {
            int r = wm * 64 + mi * 16 + lrow;
            arow[mi] = ab + (uint32_t)r * 128;
            arx[mi] = (uint32_t)(r & 7);
        }
        uint32_t brow[2], brx[2];
        #pragma unroll
        for (int nj = 0; nj < 2; nj++) {
            int r = wn * 32 + nj * 16 + lrow;
            brow[nj] = bb + (uint32_t)r * 128;
            brx[nj] = (uint32_t)(r & 7);
        }

        #pragma unroll
        for (int ks = 0; ks < 4; ks++) {
            const uint32_t ch = (uint32_t)(2 * ks + lchi);
            uint32_t af[4][4];
            #pragma unroll
            for (int mi = 0; mi < 4; mi++) {
                uint32_t addr = arow[mi] + ((ch ^ arx[mi]) << 4);
                asm volatile("ldmatrix.sync.aligned.m8n8.x4.shared.b16 {%0,%1,%2,%3}, [%4];"
                             : "=r"(af[mi][0]), "=r"(af[mi][1]), "=r"(af[mi][2]), "=r"(af[mi][3])
                             : "r"(addr));
            }
            uint32_t bf[4][2];
            #pragma unroll
            for (int nj = 0; nj < 2; nj++) {
                uint32_t addr = brow[nj] + ((ch ^ brx[nj]) << 4);
                uint32_t r0, r1, r2, r3;
                asm volatile("ldmatrix.sync.aligned.m8n8.x4.shared.b16 {%0,%1,%2,%3}, [%4];"
                             : "=r"(r0), "=r"(r1), "=r"(r2), "=r"(r3) : "r"(addr));
                bf[nj * 2 + 0][0] = r0; bf[nj * 2 + 0][1] = r2;
                bf[nj * 2 + 1][0] = r1; bf[nj * 2 + 1][1] = r3;
            }
            #pragma unroll
            for (int mi = 0; mi < 4; mi++)
                #pragma unroll
                for (int ni = 0; ni < 4; ni++) {
                    asm volatile(
                        "mma.sync.aligned.m16n8k16.row.col.f32.f16.f16.f32 "
                        "{%0,%1,%2,%3}, {%4,%5,%6,%7}, {%8,%9}, {%0,%1,%2,%3};"
                        : "+f"(acc[mi][ni][0]), "+f"(acc[mi][ni][1]),
                          "+f"(acc[mi][ni][2]), "+f"(acc[mi][ni][3])
                        : "r"(af[mi][0]), "r"(af[mi][1]), "r"(af[mi][2]), "r"(af[mi][3]),
                          "r"(bf[ni][0]), "r"(bf[ni][1]));
                }
        }
        __syncthreads();
    }

    #pragma unroll
    for (int mi = 0; mi < 4; mi++) {
        #pragma unroll
        for (int ni = 0; ni < 4; ni++) {
            int row = m0 + wm * 64 + mi * 16 + g;
            int col = n0 + wn * 32 + ni * 8 + tg * 2;
            if (col < N) {
                size_t o0 = (size_t)row * N + col;
                size_t o1 = (size_t)(row + 8) * N + col;
                float2 v0 = make_float2(acc[mi][ni][0], acc[mi][ni][1]);
                float2 v1 = make_float2(acc[mi][ni][2], acc[mi][ni][3]);
                if (RESID) {
                    float2 r0 = *reinterpret_cast<const float2*>(&R[o0]);
                    float2 r1 = *reinterpret_cast<const float2*>(&R[o1]);
                    v0.x += r0.x; v0.y += r0.y;
                    v1.x += r1.x; v1.y += r1.y;
                }
                *reinterpret_cast<float2*>(&C[o0]) = v0;
                *reinterpret_cast<float2*>(&C[o1]) = v1;
                if (HOUT) {
                    __half2 h0 = __floats2half2_rn(v0.x, v0.y);
                    __half2 h1 = __floats2half2_rn(v1.x, v1.y);
                    *reinterpret_cast<__half2*>(&Ch[o0]) = h0;
                    *reinterpret_cast<__half2*>(&Ch[o1]) = h1;
                }
            }
        }
    }
}

// ---------------- embed LN ----------------
__global__ __launch_bounds__(256)
void ln1_kernel(const float* __restrict__ tmp, const float* __restrict__ eb,
                const float* __restrict__ w, const float* __restrict__ bias,
                float* __restrict__ H, __half* __restrict__ Hh)
{
    int row = blockIdx.x;
    int b = row / TLEN, t = row % TLEN;
    const float* src = tmp + (size_t)row * D_MODEL;
    float v[2]; float s = 0.f, ss = 0.f;
    #pragma unroll
    for (int i = 0; i < 2; i++) {
        int j = threadIdx.x + i * 256;
        float val = src[j] + eb[j];
        v[i] = val; s += val; ss += val * val;
    }
    block_reduce2(s, ss);
    float m = s * (1.f / D_MODEL);
    float var = fmaxf(ss * (1.f / D_MODEL) - m * m, 0.f);
    float inv = rsqrtf(var + LN_EPS);
    size_t rf = ((size_t)b * TLEN + t) * D_MODEL;
    size_t rb = ((size_t)(BATCH + b) * TLEN + (TLEN - 1 - t)) * D_MODEL;
    #pragma unroll
    for (int i = 0; i < 2; i++) {
        int j = threadIdx.x + i * 256;
        float o = (v[i] - m) * inv * w[j] + bias[j];
        H[rf + j] = o;  H[rb + j] = o;
        __half oh = __float2half_rn(o);
        Hh[rf + j] = oh; Hh[rb + j] = oh;
    }
}

// ---------------- conv over B/C columns only + dt/dA tail ----------------
__global__ __launch_bounds__(256)
void conv_bc_kernel(const float* __restrict__ Z,
                    const float* __restrict__ cw0, const float* __restrict__ cw1,
                    const float* __restrict__ cb0, const float* __restrict__ cb1,
                    const float* __restrict__ db0, const float* __restrict__ db1,
                    const float* __restrict__ al0, const float* __restrict__ al1,
                    float* __restrict__ BC, float* __restrict__ dA, float* __restrict__ dt)
{
    long long idx = (long long)blockIdx.x * blockDim.x + threadIdx.x;
    const long long NBC = (long long)GBT * 2 * DSTATE;
    if (idx < NBC) {
        int n = (int)(idx % (2 * DSTATE));
        int gt = (int)(idx / (2 * DSTATE));
        int t = gt % TLEN;
        bool back = gt >= BT;
        int c = D_INNER + n;
        const float* cw = back ? cw1 : cw0;
        const float* cb = back ? cb1 : cb0;
        float acc = cb[c];
        #pragma unroll
        for (int j = 0; j < DCONV; j++) {
            int tt = t - (DCONV - 1) + j;
            if (tt >= 0)
                acc = fmaf(cw[c * DCONV + j],
                           Z[(size_t)(gt - (DCONV - 1) + j) * D_IN_PROJ + D_INNER + c], acc);
        }
        BC[idx] = siluf(acc);
    } else {
        long long j = idx - NBC;
        if (j >= (long long)GBT * NHEADS) return;
        int h = (int)(j % NHEADS);
        int row = (int)(j / NHEADS);
        bool back = row >= BT;
        float raw = Z[(size_t)row * D_IN_PROJ + D_INNER + CONV_DIM + h] + (back ? db1 : db0)[h];
        float d = softplusf(raw);
        float Av = expf((back ? al1 : al0)[h]);
        dt[j] = d;
        dA[j] = expf(-Av * d);
    }
}

// ---------------- two-pass chunked selective scan ----------------
struct SDR { float z, a, dt; float bb[DSTATE]; float cc[DSTATE]; };
struct SDB { float z, a, dt; float bb[DSTATE]; };

__device__ __forceinline__ SDR load_raw(const float* __restrict__ Zx,
                                        const float* __restrict__ BC,
                                        const float* __restrict__ dA,
                                        const float* __restrict__ dtv,
                                        size_t row)
{
    SDR d;
    d.z = Zx[row * D_IN_PROJ];
    const float4* bp = reinterpret_cast<const float4*>(BC + row * 2 * DSTATE);
    #pragma unroll
    for (int i = 0; i < 4; i++) {
        float4 b = bp[i];
        d.bb[4 * i + 0] = b.x; d.bb[4 * i + 1] = b.y; d.bb[4 * i + 2] = b.z; d.bb[4 * i + 3] = b.w;
        float4 c = bp[4 + i];
        d.cc[4 * i + 0] = c.x; d.cc[4 * i + 1] = c.y; d.cc[4 * i + 2] = c.z; d.cc[4 * i + 3] = c.w;
    }
    d.a  = dA[row * NHEADS];
    d.dt = dtv[row * NHEADS];
    return d;
}

__device__ __forceinline__ SDB load_rawB(const float* __restrict__ Zx,
                                         const float* __restrict__ BC,
                                         const float* __restrict__ dA,
                                         const float* __restrict__ dtv,
                                         size_t row)
{
    SDB d;
    d.z = Zx[row * D_IN_PROJ];
    const float4* bp = reinterpret_cast<const float4*>(BC + row * 2 * DSTATE);
    #pragma unroll
    for (int i = 0; i < 4; i++) {
        float4 b = bp[i];
        d.bb[4 * i + 0] = b.x; d.bb[4 * i + 1] = b.y; d.bb[4 * i + 2] = b.z; d.bb[4 * i + 3] = b.w;
    }
    d.a  = dA[row * NHEADS];
    d.dt = dtv[row * NHEADS];
    return d;
}

__device__ __forceinline__ float scan_step_x(float s[DSTATE], const SDR& d, float xs, float Dv)
{
    float xdt = xs * d.dt;
    float y0 = 0.f, y1 = 0.f, y2 = 0.f, y3 = 0.f;
    #pragma unroll
    for (int n = 0; n < DSTATE; n += 4) {
        s[n + 0] = fmaf(d.a, s[n + 0], xdt * d.bb[n + 0]); y0 = fmaf(s[n + 0], d.cc[n + 0], y0);
        s[n + 1] = fmaf(d.a, s[n + 1], xdt * d.bb[n + 1]); y1 = fmaf(s[n + 1], d.cc[n + 1], y1);
        s[n + 2] = fmaf(d.a, s[n + 2], xdt * d.bb[n + 2]); y2 = fmaf(s[n + 2], d.cc[n + 2], y2);
        s[n + 3] = fmaf(d.a, s[n + 3], xdt * d.bb[n + 3]); y3 = fmaf(s[n + 3], d.cc[n + 3], y3);
    }
    return (y0 + y1) + (y2 + y3) + Dv * xs;
}

__device__ __forceinline__ void state_step(float s[DSTATE], const SDB& d, float xs)
{
    float xdt = xs * d.dt;
    #pragma unroll
    for (int n = 0; n < DSTATE; n++)
        s[n] = fmaf(d.a, s[n], xdt * d.bb[n]);
}

#define CONV_STEP(zin, xs_out)                                                            \
    float xs_out = siluf(fmaf(cwv.w, (zin), fmaf(cwv.z, w2, fmaf(cwv.y, w1, fmaf(cwv.x, w0, cbv))))); \
    w0 = w1; w1 = w2; w2 = (zin);

// pass 1: state-only per-chunk scan, chunks 0..NCH-2 only (last chunk's E unused)
__global__ __launch_bounds__(HEADDIM)
void scan_pass1(const float* __restrict__ Z, const float* __restrict__ BC,
                const float* __restrict__ dA, const float* __restrict__ dtv,
                const float* __restrict__ cw0, const float* __restrict__ cw1,
                const float* __restrict__ cb0, const float* __restrict__ cb1,
                float* __restrict__ E, float* __restrict__ Pf)
{
    int bc = blockIdx.x;                 // gh*NCH1 + c, c in [0, NCH1)
    int gh = bc / NCH1, c = bc % NCH1;
    int g = gh / NHEADS, h = gh % NHEADS;
    int p = threadIdx.x;
    bool back = g >= BATCH;
    size_t rowB = (size_t)g * TLEN + (size_t)c * CHUNK;
    int hp = h * HEADDIM + p;

    const float4 cwv = *reinterpret_cast<const float4*>((back ? cw1 : cw0) + hp * DCONV);
    const float cbv = (back ? cb1 : cb0)[hp];
    const float* Zx = Z + D_INNER + hp;

    float w0 = 0.f, w1 = 0.f, w2 = 0.f;
    if (c > 0) {
        w0 = Zx[(rowB - 3) * D_IN_PROJ];
        w1 = Zx[(rowB - 2) * D_IN_PROJ];
        w2 = Zx[(rowB - 1) * D_IN_PROJ];
    }

    const float* dAh = dA + h;
    const float* dth = dtv + h;

    float s[DSTATE];
    #pragma unroll
    for (int n = 0; n < DSTATE; n++) s[n] = 0.f;
    float P = 1.f;

    SDB a = load_rawB(Zx, BC, dAh, dth, rowB + 0);
    SDB b = load_rawB(Zx, BC, dAh, dth, rowB + 1);
    for (int t = 0; t < CHUNK; t += 4) {
        SDB cc = load_rawB(Zx, BC, dAh, dth, rowB + t + 2);
        SDB dd = load_rawB(Zx, BC, dAh, dth, rowB + t + 3);
        { CONV_STEP(a.z, xs); state_step(s, a, xs); P *= a.a; }
        { CONV_STEP(b.z, xs); state_step(s, b, xs); P *= b.a; }
        if (t + 4 < CHUNK) {
            a = load_rawB(Zx, BC, dAh, dth, rowB + t + 4);
            b = load_rawB(Zx, BC, dAh, dth, rowB + t + 5);
        }
        { CONV_STEP(cc.z, xs); state_step(s, cc, xs); P *= cc.a; }
        { CONV_STEP(dd.z, xs); state_step(s, dd, xs); P *= dd.a; }
    }

    size_t eb = (((size_t)gh * NCH + c) * HEADDIM + p) * DSTATE;
    float4* Ep = reinterpret_cast<float4*>(E + eb);
    #pragma unroll
    for (int i = 0; i < 4; i++)
        Ep[i] = make_float4(s[4*i], s[4*i+1], s[4*i+2], s[4*i+3]);
    if (p == 0) Pf[gh * NCH + c] = P;
}

// phase 2: sequential chunk-state recurrence per (g,h); no fold for last chunk
__global__ __launch_bounds__(HEADDIM)
void scan2_kernel(const float* __restrict__ E, const float* __restrict__ Pf,
                  float* __restrict__ S0)
{
    int gh = blockIdx.x;
    int p = threadIdx.x;
    float s0[DSTATE];
    #pragma unroll
    for (int n = 0; n < DSTATE; n++) s0[n] = 0.f;

    for (int c = 0; c < NCH; c++) {
        size_t base = (((size_t)gh * NCH + c) * HEADDIM + p) * DSTATE;
        float4* So = reinterpret_cast<float4*>(S0 + base);
        #pragma unroll
        for (int i = 0; i < 4; i++)
            So[i] = make_float4(s0[4*i], s0[4*i+1], s0[4*i+2], s0[4*i+3]);
        if (c == NCH - 1) break;
        float Pc = Pf[gh * NCH + c];
        const float4* Ep = reinterpret_cast<const float4*>(E + base);
        #pragma unroll
        for (int i = 0; i < 4; i++) {
            float4 e = Ep[i];
            s0[4*i+0] = fmaf(Pc, s0[4*i+0], e.x);
            s0[4*i+1] = fmaf(Pc, s0[4*i+1], e.y);
            s0[4*i+2] = fmaf(Pc, s0[4*i+2], e.z);
            s0[4*i+3] = fmaf(Pc, s0[4*i+3], e.w);
        }
    }
}

// pass 2: full local scan initialized with s0; writes final Y (fp16) once
__global__ __launch_bounds__(HEADDIM)
void scan_pass2(const float* __restrict__ Z, const float* __restrict__ BC,
                const float* __restrict__ dA, const float* __restrict__ dtv,
                const float* __restrict__ cw0, const float* __restrict__ cw1,
                const float* __restrict__ cb0, const float* __restrict__ cb1,
                const float* __restrict__ D0, const float* __restrict__ D1,
                const float* __restrict__ S0, __half* __restrict__ Y)
{
    int bc = blockIdx.x;
    int gh = bc / NCH, c = bc % NCH;
    int g = gh / NHEADS, h = gh % NHEADS;
    int p = threadIdx.x;
    bool back = g >= BATCH;
    float Dv = (back ? D1 : D0)[h];
    size_t rowB = (size_t)g * TLEN + (size_t)c * CHUNK;
    int hp = h * HEADDIM + p;

    const float4 cwv = *reinterpret_cast<const float4*>((back ? cw1 : cw0) + hp * DCONV);
    const float cbv = (back ? cb1 : cb0)[hp];
    const float* Zx = Z + D_INNER + hp;

    float w0 = 0.f, w1 = 0.f, w2 = 0.f;
    if (c > 0) {
        w0 = Zx[(rowB - 3) * D_IN_PROJ];
        w1 = Zx[(rowB - 2) * D_IN_PROJ];
        w2 = Zx[(rowB - 1) * D_IN_PROJ];
    }

    const float* dAh = dA + h;
    const float* dth = dtv + h;

    float s[DSTATE];
    {
        const float4* So = reinterpret_cast<const float4*>(
            S0 + ((size_t)bc * HEADDIM + p) * DSTATE);
        #pragma unroll
        for (int i = 0; i < 4; i++) {
            float4 v = So[i];
            s[4*i] = v.x; s[4*i+1] = v.y; s[4*i+2] = v.z; s[4*i+3] = v.w;
        }
    }

    SDR a = load_raw(Zx, BC, dAh, dth, rowB + 0);
    SDR b = load_raw(Zx, BC, dAh, dth, rowB + 1);
    for (int t = 0; t < CHUNK; t += 4) {
        SDR cc = load_raw(Zx, BC, dAh, dth, rowB + t + 2);
        SDR dd = load_raw(Zx, BC, dAh, dth, rowB + t + 3);
        { CONV_STEP(a.z, xs); Y[(rowB + t + 0) * D_INNER + hp] = __float2half_rn(scan_step_x(s, a, xs, Dv)); }
        { CONV_STEP(b.z, xs); Y[(rowB + t + 1) * D_INNER + hp] = __float2half_rn(scan_step_x(s, b, xs, Dv)); }
        if (t + 4 < CHUNK) {
            a = load_raw(Zx, BC, dAh, dth, rowB + t + 4);
            b = load_raw(Zx, BC, dAh, dth, rowB + t + 5);
        }
        { CONV_STEP(cc.z, xs); Y[(rowB + t + 2) * D_INNER + hp] = __float2half_rn(scan_step_x(s, cc, xs, Dv)); }
        { CONV_STEP(dd.z, xs); Y[(rowB + t + 3) * D_INNER + hp] = __float2half_rn(scan_step_x(s, dd, xs, Dv)); }
    }
}

// ---------------- gate + RMSNorm -> fp16 G (Y fp16, z fp32) ----------------
__global__ __launch_bounds__(256)
void gate_rms_kernel(const float* __restrict__ Z, const __half* __restrict__ Y,
                     __half* __restrict__ Gh,
                     const float* __restrict__ rw0, const float* __restrict__ rw1)
{
    int row = blockIdx.x;
    const float* rw = (row < BT) ? rw0 : rw1;
    const float* zr = Z + (size_t)row * D_IN_PROJ;
    const __half* yr = Y + (size_t)row * D_INNER;
    __half* go = Gh + (size_t)row * D_INNER;
    float v[4]; float ss = 0.f;
    #pragma unroll
    for (int i = 0; i < 4; i++) {
        int j = threadIdx.x + i * 256;
        float gv = __half2float(yr[j]) * siluf(zr[j]);
        v[i] = gv; ss += gv * gv;
    }
    float dummy = 0.f;
    block_reduce2(ss, dummy);
    float inv = rsqrtf(ss * (1.f / D_INNER) + LN_EPS);
    #pragma unroll
    for (int i = 0; i < 4; i++) {
        int j = threadIdx.x + i * 256;
        go[j] = __float2half_rn(v[i] * inv * rw[j]);
    }
}

// ---------------- final concat + layernorm ----------------
__global__ __launch_bounds__(256)
void final_kernel(const float* __restrict__ H, const float* __restrict__ w,
                  const float* __restrict__ bias, float* __restrict__ out)
{
    int row = blockIdx.x;
    int b = row / TLEN, t = row % TLEN;
    const float* hf = H + ((size_t)b * TLEN + t) * D_MODEL;
    const float* hb = H + ((size_t)(BATCH + b) * TLEN + (TLEN - 1 - t)) * D_MODEL;
    float v[4]; float s = 0.f, ss = 0.f;
    #pragma unroll
    for (int i = 0; i < 4; i++) {
        int j = threadIdx.x + i * 256;
        float val = (i < 2) ? hf[j] : hb[j - D_MODEL];
        v[i] = val; s += val; ss += val * val;
    }
    block_reduce2(s, ss);
    const float invN = 1.f / (2 * D_MODEL);
    float m = s * invN;
    float var = fmaxf(ss * invN - m * m, 0.f);
    float inv = rsqrtf(var + LN_EPS);
    float* o = out + (size_t)row * (2 * D_MODEL);
    #pragma unroll
    for (int i = 0; i < 4; i++) {
        int j = threadIdx.x + i * 256;
        o[j] = (v[i] - m) * inv * w[j] + bias[j];
    }
}

// ---------------- launcher ----------------
extern "C" void kernel_launch(void* const* d_in, const int* in_sizes, int n_in,
                              void* d_out, int out_size)
{
    const float* x        = (const float*)d_in[0];
    const float* embed_w  = (const float*)d_in[1];
    const float* embed_b  = (const float*)d_in[2];
    const float* ln1_w    = (const float*)d_in[3];
    const float* ln1_b    = (const float*)d_in[4];
    const float* lnout_w  = (const float*)d_in[5];
    const float* lnout_b  = (const float*)d_in[6];
    const float* in_w[2]    = {(const float*)d_in[7],  (const float*)d_in[15]};
    const float* conv_w[2]  = {(const float*)d_in[8],  (const float*)d_in[16]};
    const float* conv_b[2]  = {(const float*)d_in[9],  (const float*)d_in[17]};
    const float* dt_bias[2] = {(const float*)d_in[10], (const float*)d_in[18]};
    const float* A_log[2]   = {(const float*)d_in[11], (const float*)d_in[19]};
    const float* Dp[2]      = {(const float*)d_in[12], (const float*)d_in[20]};
    const float* rms_w[2]   = {(const float*)d_in[13], (const float*)d_in[21]};
    const float* out_w[2]   = {(const float*)d_in[14], (const float*)d_in[22]};
    float* out = (float*)d_out;

    float *pH, *pZ, *pBC, *pdA, *pdt, *ptmp, *pE, *pS0, *pPf;
    __half *pHh, *pYh, *pGh, *pxh, *pewh, *piwh, *powh;
    cudaGetSymbolAddress((void**)&pH,   g_H);
    cudaGetSymbolAddress((void**)&pHh,  g_Hh);
    cudaGetSymbolAddress((void**)&pZ,   g_Z);
    cudaGetSymbolAddress((void**)&pBC,  g_BC);
    cudaGetSymbolAddress((void**)&pdA,  g_dA);
    cudaGetSymbolAddress((void**)&pdt,  g_dt);
    cudaGetSymbolAddress((void**)&pYh,  g_Yh);
    cudaGetSymbolAddress((void**)&pGh,  g_Gh);
    cudaGetSymbolAddress((void**)&ptmp, g_tmp);
    cudaGetSymbolAddress((void**)&pxh,  g_xh);
    cudaGetSymbolAddress((void**)&pewh, g_ewh);
    cudaGetSymbolAddress((void**)&piwh, g_iwh);
    cudaGetSymbolAddress((void**)&powh, g_owh);
    cudaGetSymbolAddress((void**)&pE,   g_E);
    cudaGetSymbolAddress((void**)&pS0,  g_S0);
    cudaGetSymbolAddress((void**)&pPf,  g_Pf);

    cudaFuncSetAttribute(tc_gemm<false,false>, cudaFuncAttributeMaxDynamicSharedMemorySize, TCG_SMEM);
    cudaFuncSetAttribute(tc_gemm<true,true>,   cudaFuncAttributeMaxDynamicSharedMemorySize, TCG_SMEM);

    const size_t IWSZ = (size_t)NLAYERS * D_IN_PROJ * D_MODEL;
    const size_t OWSZ = (size_t)NLAYERS * D_MODEL * D_INNER;

    {
        F2HSeg s0 = { x,        pxh,         (long long)BT * INPUT_DIM };
        F2HSeg s1 = { embed_w,  pewh,        (long long)D_MODEL * INPUT_DIM };
        F2HSeg s2 = { in_w[0],  piwh,        (long long)IWSZ };
        F2HSeg s3 = { in_w[1],  piwh + IWSZ, (long long)IWSZ };
        F2HSeg s4 = { out_w[0], powh,        (long long)OWSZ };
        F2HSeg s5 = { out_w[1], powh + OWSZ, (long long)OWSZ };
        long long total = s0.n + s1.n + s2.n + s3.n + s4.n + s5.n;
        f2h6_kernel<<<(unsigned)((total / 8 + 255) / 256), 256>>>(s0, s1, s2, s3, s4, s5);
    }

    tc_gemm<false,false><<<dim3(D_MODEL / 128, BT / 128), 256, TCG_SMEM>>>(
        pxh, pewh, pewh, nullptr, ptmp, nullptr, BT, D_MODEL, INPUT_DIM);
    ln1_kernel<<<BT, 256>>>(ptmp, embed_b, ln1_w, ln1_b, pH, pHh);

    for (int L = 0; L < NLAYERS; L++) {
        const __half* iw0 = piwh + (size_t)L * D_IN_PROJ * D_MODEL;
        const __half* iw1 = piwh + IWSZ + (size_t)L * D_IN_PROJ * D_MODEL;
        const __half* ow0 = powh + (size_t)L * D_MODEL * D_INNER;
        const __half* ow1 = powh + OWSZ + (size_t)L * D_MODEL * D_INNER;
        const float* cw0 = conv_w[0] + (size_t)L * CONV_DIM * DCONV;
        const float* cw1 = conv_w[1] + (size_t)L * CONV_DIM * DCONV;
        const float* cb0 = conv_b[0] + (size_t)L * CONV_DIM;
        const float* cb1 = conv_b[1] + (size_t)L * CONV_DIM;
        const float* db0 = dt_bias[0] + L * NHEADS;
        const float* db1 = dt_bias[1] + L * NHEADS;
        const float* al0 = A_log[0] + L * NHEADS;
        const float* al1 = A_log[1] + L * NHEADS;
        const float* D0  = Dp[0] + L * NHEADS;
        const float* D1  = Dp[1] + L * NHEADS;
        const float* rw0 = rms_w[0] + (size_t)L * D_INNER;
        const float* rw1 = rms_w[1] + (size_t)L * D_INNER;

        tc_gemm<false,false><<<dim3((D_IN_PROJ + 127) / 128, GBT / 128), 256, TCG_SMEM>>>(
            pHh, iw0, iw1, nullptr, pZ, nullptr, GBT, D_IN_PROJ, D_MODEL);

        {
            long long total = (long long)GBT * 2 * DSTATE + (long long)GBT * NHEADS;
            conv_bc_kernel<<<(unsigned)((total + 255) / 256), 256>>>(
                pZ, cw0, cw1, cb0, cb1, db0, db1, al0, al1, pBC, pdA, pdt);
        }

        scan_pass1<<<GB * NHEADS * NCH1, HEADDIM>>>(
            pZ, pBC, pdA, pdt, cw0, cw1, cb0, cb1, pE, pPf);
        scan2_kernel<<<GB * NHEADS, HEADDIM>>>(pE, pPf, pS0);
        scan_pass2<<<GB * NHEADS * NCH, HEADDIM>>>(
            pZ, pBC, pdA, pdt, cw0, cw1, cb0, cb1, D0, D1, pS0, pYh);

        gate_rms_kernel<<<GBT, 256>>>(pZ, pYh, pGh, rw0, rw1);

        tc_gemm<true,true><<<dim3(D_MODEL / 128, GBT / 128), 256, TCG_SMEM>>>(
            pGh, ow0, ow1, pH, pH, pHh, GBT, D_MODEL, D_INNER);
    }

    final_kernel<<<BT, 256>>>(pH, lnout_w, lnout_b, out);
}